// round 14
// baseline (speedup 1.0000x reference)
#include <cuda_runtime.h>
#include <cuda_fp16.h>
#include <cstdint>

#define NN 100000
#define EE 3200000
#define HID 32
#define DIN 128
#define SCAN_B 256
#define AGG_T 512
#define NREP 32                                 // stat replicas per layer

// ---------------- scratch ----------------
__device__ float g_tmp[NN * HID];   // dinv_r * (h @ W)  (gather source)
__device__ float g_acc[NN * HID];   // conv result
__device__ unsigned long long g_hist[NN];  // packed {count:12 | weight_fx:52}
__device__ float g_deg[NN];         // dinv
__device__ int   g_cnt[NN];         // counts, then CSR cursor
__device__ int   g_off[NN + 1];     // CSR offsets
__device__ __align__(16) int2 g_edge[EE + 2];   // CSR: {src, w bits}; +tail pad
__device__ int   g_bsum[512];       // scan block sums
__device__ float g_statsR[3 * NREP * 64];  // replicated BN partials

// ---------------- prep ----------------
__global__ void k_init(int n) {
    int i = blockIdx.x * blockDim.x + threadIdx.x;
    if (i < n) g_hist[i] = 0ULL;
    if (i < 3 * NREP * 64) g_statsR[i] = 0.f;
}

// one packed atomic per edge: count += 1 (bit 52), weight += w * 2^32
__global__ void k_hist(const int* __restrict__ ei,
                       const float* __restrict__ w, int e_cnt, int n) {
    int e = blockIdx.x * blockDim.x + threadIdx.x;
    if (e < e_cnt) {
        int c = ei[e_cnt + e];
        c = min(max(c, 0), n - 1);
        unsigned long long wf =
            (unsigned long long)(fmaxf(w[e], 0.f) * 4294967296.0f + 0.5f);
        atomicAdd(&g_hist[c], (1ULL << 52) | wf);
    }
}

// scan_a fused with unpack + dinv
__global__ void k_scan_a(int n) {
    __shared__ int sh[SCAN_B];
    int i = blockIdx.x * SCAN_B + threadIdx.x;
    int cnt = 0;
    if (i < n) {
        unsigned long long h = g_hist[i];
        cnt = (int)(h >> 52);
        float wsum = (float)(h & ((1ULL << 52) - 1ULL)) * 2.3283064365386963e-10f
                     + 1.0f;   // + self-loop
        g_deg[i] = rsqrtf(wsum);
        g_cnt[i] = cnt;
    }
    sh[threadIdx.x] = cnt;
    __syncthreads();
    for (int off = SCAN_B / 2; off > 0; off >>= 1) {
        if (threadIdx.x < off) sh[threadIdx.x] += sh[threadIdx.x + off];
        __syncthreads();
    }
    if (threadIdx.x == 0) g_bsum[blockIdx.x] = sh[0];
}

// scan_c computes its own global offset from g_bsum
__global__ void k_scan_c(int n, int e_cnt) {
    __shared__ int sh[SCAN_B];
    __shared__ int base_s;
    int tid = threadIdx.x;
    int s = 0;
    for (int j = tid; j < blockIdx.x; j += SCAN_B) s += g_bsum[j];
    sh[tid] = s;
    __syncthreads();
    for (int off = SCAN_B / 2; off > 0; off >>= 1) {
        if (tid < off) sh[tid] += sh[tid + off];
        __syncthreads();
    }
    if (tid == 0) base_s = sh[0];
    __syncthreads();
    int base = base_s;
    __syncthreads();

    int i = blockIdx.x * SCAN_B + tid;
    int c = (i < n) ? g_cnt[i] : 0;
    sh[tid] = c;
    __syncthreads();
    for (int off = 1; off < SCAN_B; off <<= 1) {
        int v = (tid >= off) ? sh[tid - off] : 0;
        __syncthreads();
        sh[tid] += v;
        __syncthreads();
    }
    if (i < n) {
        int off = base + sh[tid] - c;
        g_off[i] = off;
        g_cnt[i] = off;
    }
    if (blockIdx.x == 0 && tid == 0) g_off[n] = e_cnt;
}

// stores raw {src, w} — norm factored into tmp/epilogue
__global__ void k_csr_scatter(const int* __restrict__ ei,
                              const float* __restrict__ w, int e_cnt, int n) {
    int e = blockIdx.x * blockDim.x + threadIdx.x;
    if (e < e_cnt) {
        int r = ei[e];
        int c = ei[e_cnt + e];
        r = min(max(r, 0), n - 1);
        c = min(max(c, 0), n - 1);
        int pos = atomicAdd(&g_cnt[c], 1);
        g_edge[pos] = make_int2(r, __float_as_int(w[e]));
    }
}

// ---------------- transforms (scaled by dinv at write) ----------------
__global__ void k_gemm128(const float* __restrict__ x,
                          const float* __restrict__ W, int n) {
    __shared__ float Ws[DIN * HID];
    __shared__ float xs[8][DIN];
    int tid = threadIdx.x;
    for (int i = tid; i < DIN * HID; i += 256) Ws[i] = W[i];
    __syncthreads();
    int warp = tid >> 5, lane = tid & 31;
    int r = blockIdx.x * 8 + warp;
    if (r >= n) return;
#pragma unroll
    for (int j = 0; j < 4; j++)
        xs[warp][j * 32 + lane] = x[r * DIN + j * 32 + lane];
    __syncwarp();
    float sum = 0.f;
#pragma unroll
    for (int k = 0; k < DIN; k++) sum += xs[warp][k] * Ws[k * HID + lane];
    g_tmp[r * HID + lane] = sum * g_deg[r];
}

// prologue reduces the NREP stat replicas of the previous layer
__global__ void k_gemm32_bn(const float* __restrict__ W,
                            const float* __restrict__ g,
                            const float* __restrict__ be,
                            int n, float invN, int layerm1) {
    __shared__ float Ws[HID * HID];
    __shared__ float bn_s[HID], bn_b[HID];
    int tid = threadIdx.x;
    for (int i = tid; i < HID * HID; i += 256) Ws[i] = W[i];
    if (tid < 64) {
        const float* base = &g_statsR[layerm1 * NREP * 64];
        float s = 0.f;
#pragma unroll
        for (int r2 = 0; r2 < NREP; r2++) s += base[r2 * 64 + tid];
        if (tid < 32) bn_s[tid] = s;        // stash sum
        else          bn_b[tid - 32] = s;   // stash sumsq
    }
    __syncthreads();
    if (tid < HID) {
        float mu  = bn_s[tid] * invN;
        float var = bn_b[tid] * invN - mu * mu;
        float sc  = rsqrtf(var + 1e-5f) * g[tid];
        bn_s[tid] = sc;
        bn_b[tid] = be[tid] - mu * sc;
    }
    __syncthreads();
    int warp = tid >> 5, lane = tid & 31;
    int r = blockIdx.x * 8 + warp;
    if (r >= n) return;
    float mine = fmaxf(g_acc[r * HID + lane] * bn_s[lane] + bn_b[lane], 0.f);
    float sum = 0.f;
#pragma unroll
    for (int k = 0; k < HID; k++) {
        float xv = __shfl_sync(0xffffffffu, mine, k);
        sum += xv * Ws[k * HID + lane];
    }
    g_tmp[r * HID + lane] = sum * g_deg[r];
}

// ---------------- CSR gather-aggregate ----------------
// metadata read as int4 (2 edges per LDG.128) to halve metadata LDG issues.
__global__ void __launch_bounds__(AGG_T)
k_aggregate(const float* __restrict__ b, int n, int layer,
            float* __restrict__ out) {
    int gid = blockIdx.x * AGG_T + threadIdx.x;
    int v = gid >> 5;
    int lane = gid & 31;
    int warp = threadIdx.x >> 5;
    float acc = 0.f;
    if (v < n) {
        int beg = g_off[v];
        int end = g_off[v + 1];
        float inner = g_tmp[v * HID + lane];   // self-loop (w=1)
        int i = beg;
        // peel to even index for int4 alignment
        if ((i & 1) && i < end) {
            int2 e0 = g_edge[i];
            inner += __int_as_float(e0.y) * g_tmp[e0.x * HID + lane];
            i++;
        }
        const int4* e4 = (const int4*)g_edge;
        // 8 edges per iter via 4x LDG.128 metadata
        for (; i + 8 <= end; i += 8) {
            int h = i >> 1;
            int4 a = e4[h + 0];   // {src0,w0,src1,w1}
            int4 b2 = e4[h + 1];
            int4 c2 = e4[h + 2];
            int4 d2 = e4[h + 3];
            float f0 = g_tmp[a.x  * HID + lane];
            float f1 = g_tmp[a.z  * HID + lane];
            float f2 = g_tmp[b2.x * HID + lane];
            float f3 = g_tmp[b2.z * HID + lane];
            float f4 = g_tmp[c2.x * HID + lane];
            float f5 = g_tmp[c2.z * HID + lane];
            float f6 = g_tmp[d2.x * HID + lane];
            float f7 = g_tmp[d2.z * HID + lane];
            inner += __int_as_float(a.y)  * f0;
            inner += __int_as_float(a.w)  * f1;
            inner += __int_as_float(b2.y) * f2;
            inner += __int_as_float(b2.w) * f3;
            inner += __int_as_float(c2.y) * f4;
            inner += __int_as_float(c2.w) * f5;
            inner += __int_as_float(d2.y) * f6;
            inner += __int_as_float(d2.w) * f7;
        }
        if (i + 4 <= end) {
            int h = i >> 1;
            int4 a = e4[h + 0];
            int4 b2 = e4[h + 1];
            float f0 = g_tmp[a.x  * HID + lane];
            float f1 = g_tmp[a.z  * HID + lane];
            float f2 = g_tmp[b2.x * HID + lane];
            float f3 = g_tmp[b2.z * HID + lane];
            inner += __int_as_float(a.y)  * f0;
            inner += __int_as_float(a.w)  * f1;
            inner += __int_as_float(b2.y) * f2;
            inner += __int_as_float(b2.w) * f3;
            i += 4;
        }
        for (; i < end; i++) {
            int2 e0 = g_edge[i];
            inner += __int_as_float(e0.y) * g_tmp[e0.x * HID + lane];
        }
        acc = b[lane] + g_deg[v] * inner;
        if (out) out[v * HID + lane] = fmaxf(acc, 0.f);
        else     g_acc[v * HID + lane] = acc;
    }
    if (layer < 3) {   // BN stats via replicated atomics
        __shared__ float sh[16][64];
        float a = (v < n) ? acc : 0.f;
        sh[warp][lane]      = a;
        sh[warp][32 + lane] = a * a;
        __syncthreads();
        if (threadIdx.x < 64) {
            float t = 0.f;
#pragma unroll
            for (int w = 0; w < 16; w++) t += sh[w][threadIdx.x];
            int rep = blockIdx.x & (NREP - 1);
            atomicAdd(&g_statsR[(layer * NREP + rep) * 64 + threadIdx.x], t);
        }
    }
}

// ---------------- launch ----------------
extern "C" void kernel_launch(void* const* d_in, const int* in_sizes, int n_in,
                              void* d_out, int out_size) {
    const float* x  = (const float*)d_in[0];
    const int*   ei = (const int*)d_in[1];     // int32 (harness dtype)
    const float* w  = (const float*)d_in[2];
    const float* W0 = (const float*)d_in[3];
    const float* b0 = (const float*)d_in[4];
    const float* W1 = (const float*)d_in[5];
    const float* b1 = (const float*)d_in[6];
    const float* W2 = (const float*)d_in[7];
    const float* b2 = (const float*)d_in[8];
    const float* W3 = (const float*)d_in[9];
    const float* b3 = (const float*)d_in[10];
    const float* g0 = (const float*)d_in[11];
    const float* be0 = (const float*)d_in[12];
    const float* g1 = (const float*)d_in[13];
    const float* be1 = (const float*)d_in[14];
    const float* g2 = (const float*)d_in[15];
    const float* be2 = (const float*)d_in[16];
    float* out = (float*)d_out;

    const int n = in_sizes[0] / DIN;        // 100000
    const int e = in_sizes[2];              // 3200000
    const float invN = 1.0f / (float)n;

    const int TB = 256;
    const int gN   = (n + TB - 1) / TB;
    const int gE   = (e + TB - 1) / TB;
    const int gAgg = (n * 32 + AGG_T - 1) / AGG_T;  // 6250
    const int gRow = (n + 7) / 8;
    const int nb   = (n + SCAN_B - 1) / SCAN_B;     // 391

    // ---- CSR + normalization precompute ----
    k_init<<<gN, TB>>>(n);
    k_hist<<<gE, TB>>>(ei, w, e, n);
    k_scan_a<<<nb, SCAN_B>>>(n);
    k_scan_c<<<nb, SCAN_B>>>(n, e);
    k_csr_scatter<<<gE, TB>>>(ei, w, e, n);

    const float* Ws[4]  = {W0, W1, W2, W3};
    const float* bs[4]  = {b0, b1, b2, b3};
    const float* gs[3]  = {g0, g1, g2};
    const float* bes[3] = {be0, be1, be2};

    for (int layer = 0; layer < 4; layer++) {
        if (layer == 0)
            k_gemm128<<<gRow, TB>>>(x, Ws[0], n);
        else
            k_gemm32_bn<<<gRow, TB>>>(Ws[layer], gs[layer - 1],
                                      bes[layer - 1], n, invN, layer - 1);
        k_aggregate<<<gAgg, AGG_T>>>(bs[layer], n, layer,
                                     (layer == 3) ? out : nullptr);
    }
}

// round 15
// speedup vs baseline: 1.0150x; 1.0150x over previous
#include <cuda_runtime.h>
#include <cuda_fp16.h>
#include <cstdint>

#define NN 100000
#define EE 3200000
#define HID 32
#define DIN 128
#define SCAN_B 256
#define AGG_T 512
#define NREP 32                                 // stat replicas per layer

// ---------------- scratch ----------------
__device__ float g_tmp[NN * HID];   // dinv_r * (h @ W)  (gather source)
__device__ float g_acc[NN * HID];   // conv result
__device__ unsigned long long g_hist[NN];  // packed {count:12 | weight_fx:52}
__device__ float g_deg[NN];         // dinv
__device__ int   g_cnt[NN];         // counts, then CSR cursor
__device__ int   g_off[NN + 1];     // CSR offsets
__device__ int2  g_edge[EE];        // CSR: {src, float-bits of raw weight}
__device__ int   g_bsum[512];       // scan block sums
__device__ float g_statsR[3 * NREP * 64];  // replicated BN partials

// ---------------- side stream + events (created before harness checkpoint)
namespace {
struct SideStream {
    cudaStream_t s2;
    cudaEvent_t evFork, evScan, evJoin;
    SideStream() {
        cudaStreamCreateWithFlags(&s2, cudaStreamNonBlocking);
        cudaEventCreateWithFlags(&evFork, cudaEventDisableTiming);
        cudaEventCreateWithFlags(&evScan, cudaEventDisableTiming);
        cudaEventCreateWithFlags(&evJoin, cudaEventDisableTiming);
    }
};
SideStream g_ss;   // static init: runs at program start, outside capture
}

// ---------------- prep ----------------
__global__ void k_init(int n) {
    int i = blockIdx.x * blockDim.x + threadIdx.x;
    if (i < n) g_hist[i] = 0ULL;
    if (i < 3 * NREP * 64) g_statsR[i] = 0.f;
}

// one packed atomic per edge: count += 1 (bit 52), weight += w * 2^32
__global__ void k_hist(const int* __restrict__ ei,
                       const float* __restrict__ w, int e_cnt, int n) {
    int e = blockIdx.x * blockDim.x + threadIdx.x;
    if (e < e_cnt) {
        int c = ei[e_cnt + e];
        c = min(max(c, 0), n - 1);
        unsigned long long wf =
            (unsigned long long)(fmaxf(w[e], 0.f) * 4294967296.0f + 0.5f);
        atomicAdd(&g_hist[c], (1ULL << 52) | wf);
    }
}

// scan_a fused with unpack + dinv
__global__ void k_scan_a(int n) {
    __shared__ int sh[SCAN_B];
    int i = blockIdx.x * SCAN_B + threadIdx.x;
    int cnt = 0;
    if (i < n) {
        unsigned long long h = g_hist[i];
        cnt = (int)(h >> 52);
        float wsum = (float)(h & ((1ULL << 52) - 1ULL)) * 2.3283064365386963e-10f
                     + 1.0f;   // + self-loop
        g_deg[i] = rsqrtf(wsum);
        g_cnt[i] = cnt;
    }
    sh[threadIdx.x] = cnt;
    __syncthreads();
    for (int off = SCAN_B / 2; off > 0; off >>= 1) {
        if (threadIdx.x < off) sh[threadIdx.x] += sh[threadIdx.x + off];
        __syncthreads();
    }
    if (threadIdx.x == 0) g_bsum[blockIdx.x] = sh[0];
}

// scan_c computes its own global offset from g_bsum
__global__ void k_scan_c(int n, int e_cnt) {
    __shared__ int sh[SCAN_B];
    __shared__ int base_s;
    int tid = threadIdx.x;
    int s = 0;
    for (int j = tid; j < blockIdx.x; j += SCAN_B) s += g_bsum[j];
    sh[tid] = s;
    __syncthreads();
    for (int off = SCAN_B / 2; off > 0; off >>= 1) {
        if (tid < off) sh[tid] += sh[tid + off];
        __syncthreads();
    }
    if (tid == 0) base_s = sh[0];
    __syncthreads();
    int base = base_s;
    __syncthreads();

    int i = blockIdx.x * SCAN_B + tid;
    int c = (i < n) ? g_cnt[i] : 0;
    sh[tid] = c;
    __syncthreads();
    for (int off = 1; off < SCAN_B; off <<= 1) {
        int v = (tid >= off) ? sh[tid - off] : 0;
        __syncthreads();
        sh[tid] += v;
        __syncthreads();
    }
    if (i < n) {
        int off = base + sh[tid] - c;
        g_off[i] = off;
        g_cnt[i] = off;
    }
    if (blockIdx.x == 0 && tid == 0) g_off[n] = e_cnt;
}

// stores raw {src, w} — norm factored into tmp/epilogue
__global__ void k_csr_scatter(const int* __restrict__ ei,
                              const float* __restrict__ w, int e_cnt, int n) {
    int e = blockIdx.x * blockDim.x + threadIdx.x;
    if (e < e_cnt) {
        int r = ei[e];
        int c = ei[e_cnt + e];
        r = min(max(r, 0), n - 1);
        c = min(max(c, 0), n - 1);
        int pos = atomicAdd(&g_cnt[c], 1);
        g_edge[pos] = make_int2(r, __float_as_int(w[e]));
    }
}

// ---------------- transforms ----------------
// layer 0, RAW (no deg scale): depends only on x and W0 -> can run on the
// side stream concurrently with the CSR prep chain.
__global__ void k_gemm128_raw(const float* __restrict__ x,
                              const float* __restrict__ W, int n) {
    __shared__ float Ws[DIN * HID];
    __shared__ float xs[8][DIN];
    int tid = threadIdx.x;
    for (int i = tid; i < DIN * HID; i += 256) Ws[i] = W[i];
    __syncthreads();
    int warp = tid >> 5, lane = tid & 31;
    int r = blockIdx.x * 8 + warp;
    if (r >= n) return;
#pragma unroll
    for (int j = 0; j < 4; j++)
        xs[warp][j * 32 + lane] = x[r * DIN + j * 32 + lane];
    __syncwarp();
    float sum = 0.f;
#pragma unroll
    for (int k = 0; k < DIN; k++) sum += xs[warp][k] * Ws[k * HID + lane];
    g_tmp[r * HID + lane] = sum;
}

// scale g_tmp rows by dinv (coalesced; one g_deg broadcast per warp)
__global__ void k_scale(int n) {
    int idx = blockIdx.x * blockDim.x + threadIdx.x;
    if (idx < n * HID) g_tmp[idx] *= g_deg[idx >> 5];
}

// prologue reduces the NREP stat replicas of the previous layer
__global__ void k_gemm32_bn(const float* __restrict__ W,
                            const float* __restrict__ g,
                            const float* __restrict__ be,
                            int n, float invN, int layerm1) {
    __shared__ float Ws[HID * HID];
    __shared__ float bn_s[HID], bn_b[HID];
    int tid = threadIdx.x;
    for (int i = tid; i < HID * HID; i += 256) Ws[i] = W[i];
    if (tid < 64) {
        const float* base = &g_statsR[layerm1 * NREP * 64];
        float s = 0.f;
#pragma unroll
        for (int r2 = 0; r2 < NREP; r2++) s += base[r2 * 64 + tid];
        if (tid < 32) bn_s[tid] = s;        // stash sum
        else          bn_b[tid - 32] = s;   // stash sumsq
    }
    __syncthreads();
    if (tid < HID) {
        float mu  = bn_s[tid] * invN;
        float var = bn_b[tid] * invN - mu * mu;
        float sc  = rsqrtf(var + 1e-5f) * g[tid];
        bn_s[tid] = sc;
        bn_b[tid] = be[tid] - mu * sc;
    }
    __syncthreads();
    int warp = tid >> 5, lane = tid & 31;
    int r = blockIdx.x * 8 + warp;
    if (r >= n) return;
    float mine = fmaxf(g_acc[r * HID + lane] * bn_s[lane] + bn_b[lane], 0.f);
    float sum = 0.f;
#pragma unroll
    for (int k = 0; k < HID; k++) {
        float xv = __shfl_sync(0xffffffffu, mine, k);
        sum += xv * Ws[k * HID + lane];
    }
    g_tmp[r * HID + lane] = sum * g_deg[r];
}

// ---------------- CSR gather-aggregate (R13 champion core) --------------
__global__ void __launch_bounds__(AGG_T)
k_aggregate(const float* __restrict__ b, int n, int layer,
            float* __restrict__ out) {
    int gid = blockIdx.x * AGG_T + threadIdx.x;
    int v = gid >> 5;
    int lane = gid & 31;
    int warp = threadIdx.x >> 5;
    float acc = 0.f;
    if (v < n) {
        int beg = g_off[v];
        int end = g_off[v + 1];
        float inner = g_tmp[v * HID + lane];   // self-loop (w=1)
        int i = beg;
        for (; i + 8 <= end; i += 8) {
            int2 e0 = g_edge[i + 0];
            int2 e1 = g_edge[i + 1];
            int2 e2 = g_edge[i + 2];
            int2 e3 = g_edge[i + 3];
            int2 e4 = g_edge[i + 4];
            int2 e5 = g_edge[i + 5];
            int2 e6 = g_edge[i + 6];
            int2 e7 = g_edge[i + 7];
            float f0 = g_tmp[e0.x * HID + lane];
            float f1 = g_tmp[e1.x * HID + lane];
            float f2 = g_tmp[e2.x * HID + lane];
            float f3 = g_tmp[e3.x * HID + lane];
            float f4 = g_tmp[e4.x * HID + lane];
            float f5 = g_tmp[e5.x * HID + lane];
            float f6 = g_tmp[e6.x * HID + lane];
            float f7 = g_tmp[e7.x * HID + lane];
            inner += __int_as_float(e0.y) * f0;
            inner += __int_as_float(e1.y) * f1;
            inner += __int_as_float(e2.y) * f2;
            inner += __int_as_float(e3.y) * f3;
            inner += __int_as_float(e4.y) * f4;
            inner += __int_as_float(e5.y) * f5;
            inner += __int_as_float(e6.y) * f6;
            inner += __int_as_float(e7.y) * f7;
        }
        if (i + 4 <= end) {
            int2 e0 = g_edge[i + 0];
            int2 e1 = g_edge[i + 1];
            int2 e2 = g_edge[i + 2];
            int2 e3 = g_edge[i + 3];
            float f0 = g_tmp[e0.x * HID + lane];
            float f1 = g_tmp[e1.x * HID + lane];
            float f2 = g_tmp[e2.x * HID + lane];
            float f3 = g_tmp[e3.x * HID + lane];
            inner += __int_as_float(e0.y) * f0;
            inner += __int_as_float(e1.y) * f1;
            inner += __int_as_float(e2.y) * f2;
            inner += __int_as_float(e3.y) * f3;
            i += 4;
        }
        for (; i < end; i++) {
            int2 e0 = g_edge[i];
            inner += __int_as_float(e0.y) * g_tmp[e0.x * HID + lane];
        }
        acc = b[lane] + g_deg[v] * inner;
        if (out) out[v * HID + lane] = fmaxf(acc, 0.f);
        else     g_acc[v * HID + lane] = acc;
    }
    if (layer < 3) {   // BN stats via replicated atomics
        __shared__ float sh[16][64];
        float a = (v < n) ? acc : 0.f;
        sh[warp][lane]      = a;
        sh[warp][32 + lane] = a * a;
        __syncthreads();
        if (threadIdx.x < 64) {
            float t = 0.f;
#pragma unroll
            for (int w = 0; w < 16; w++) t += sh[w][threadIdx.x];
            int rep = blockIdx.x & (NREP - 1);
            atomicAdd(&g_statsR[(layer * NREP + rep) * 64 + threadIdx.x], t);
        }
    }
}

// ---------------- launch ----------------
extern "C" void kernel_launch(void* const* d_in, const int* in_sizes, int n_in,
                              void* d_out, int out_size) {
    const float* x  = (const float*)d_in[0];
    const int*   ei = (const int*)d_in[1];     // int32 (harness dtype)
    const float* w  = (const float*)d_in[2];
    const float* W0 = (const float*)d_in[3];
    const float* b0 = (const float*)d_in[4];
    const float* W1 = (const float*)d_in[5];
    const float* b1 = (const float*)d_in[6];
    const float* W2 = (const float*)d_in[7];
    const float* b2 = (const float*)d_in[8];
    const float* W3 = (const float*)d_in[9];
    const float* b3 = (const float*)d_in[10];
    const float* g0 = (const float*)d_in[11];
    const float* be0 = (const float*)d_in[12];
    const float* g1 = (const float*)d_in[13];
    const float* be1 = (const float*)d_in[14];
    const float* g2 = (const float*)d_in[15];
    const float* be2 = (const float*)d_in[16];
    float* out = (float*)d_out;

    const int n = in_sizes[0] / DIN;        // 100000
    const int e = in_sizes[2];              // 3200000
    const float invN = 1.0f / (float)n;

    const int TB = 256;
    const int gN   = (n + TB - 1) / TB;
    const int gE   = (e + TB - 1) / TB;
    const int gNH  = (n * HID + TB - 1) / TB;
    const int gAgg = (n * 32 + AGG_T - 1) / AGG_T;  // 6250
    const int gRow = (n + 7) / 8;
    const int nb   = (n + SCAN_B - 1) / SCAN_B;     // 391

    // ---- fork: layer-0 transform on side stream, CSR prep on main ----
    cudaEventRecord(g_ss.evFork, 0);
    cudaStreamWaitEvent(g_ss.s2, g_ss.evFork, 0);
    k_gemm128_raw<<<gRow, TB, 0, g_ss.s2>>>(x, W0, n);   // only needs x, W0

    k_init<<<gN, TB>>>(n);
    k_hist<<<gE, TB>>>(ei, w, e, n);
    k_scan_a<<<nb, SCAN_B>>>(n);
    cudaEventRecord(g_ss.evScan, 0);                 // g_deg ready
    k_scan_c<<<nb, SCAN_B>>>(n, e);
    k_csr_scatter<<<gE, TB>>>(ei, w, e, n);

    cudaStreamWaitEvent(g_ss.s2, g_ss.evScan, 0);
    k_scale<<<gNH, TB, 0, g_ss.s2>>>(n);             // g_tmp *= dinv
    cudaEventRecord(g_ss.evJoin, g_ss.s2);
    cudaStreamWaitEvent(0, g_ss.evJoin, 0);          // join before aggregate

    const float* Ws[4]  = {W0, W1, W2, W3};
    const float* bs[4]  = {b0, b1, b2, b3};
    const float* gs[3]  = {g0, g1, g2};
    const float* bes[3] = {be0, be1, be2};

    for (int layer = 0; layer < 4; layer++) {
        if (layer > 0)
            k_gemm32_bn<<<gRow, TB>>>(Ws[layer], gs[layer - 1],
                                      bes[layer - 1], n, invN, layer - 1);
        k_aggregate<<<gAgg, AGG_T>>>(bs[layer], n, layer,
                                     (layer == 3) ? out : nullptr);
    }
}